// round 10
// baseline (speedup 1.0000x reference)
#include <cuda_runtime.h>
#include <cuda_bf16.h>

// x: (1, 256, 512, 512) fp32 -> out: (1, 64, 512, 512), mean over groups of 4 channels.
// HW4 = 512*512/4 = 65536 float4 per channel plane (= 2^16, so decode is bit-ops).
// out[c][p] = 0.25 * (x[4c][p] + x[4c+1][p] + x[4c+2][p] + x[4c+3][p])
//
// Persistent grid-stride kernel: 592 CTAs (148 SMs x 4), software-pipelined so
// the next iteration's 4 loads are issued before the current store. Removes
// wave-transition overhead and last-wave tail imbalance of the 8192-CTA launch.

static constexpr int HW4   = (512 * 512) / 4;          // 65536 = 2^16
static constexpr int C_OUT = 64;
static constexpr unsigned TOTAL = C_OUT * HW4;         // 4,194,304 output float4
static constexpr int THREADS = 256;
static constexpr int NBLK = 148 * 4;                   // 592 persistent CTAs

__device__ __forceinline__ unsigned in_base(unsigned i) {
    // i = c*HW4 + p  ->  input index of channel 4c at position p:
    // (c*4)*HW4 + p = ((i & ~0xFFFF) << 2) | (i & 0xFFFF)
    return ((i & 0xFFFF0000u) << 2) | (i & 0xFFFFu);
}

__global__ __launch_bounds__(THREADS)
void spectral_blurrin_kernel(const float4* __restrict__ x,
                             float4* __restrict__ out) {
    const unsigned stride = (unsigned)gridDim.x * THREADS;
    unsigned i = blockIdx.x * THREADS + threadIdx.x;

    float4 a, b, d, e;
    if (i < TOTAL) {
        const unsigned base = in_base(i);
        a = __ldcs(x + base);
        b = __ldcs(x + base + HW4);
        d = __ldcs(x + base + 2 * HW4);
        e = __ldcs(x + base + 3 * HW4);
    }

    for (; i < TOTAL; i += stride) {
        // Prefetch next iteration's 4 loads before the current store.
        float4 na, nb, nd, ne;
        const unsigned ni = i + stride;
        if (ni < TOTAL) {
            const unsigned nbase = in_base(ni);
            na = __ldcs(x + nbase);
            nb = __ldcs(x + nbase + HW4);
            nd = __ldcs(x + nbase + 2 * HW4);
            ne = __ldcs(x + nbase + 3 * HW4);
        }

        float4 r;
        r.x = (a.x + b.x + d.x + e.x) * 0.25f;
        r.y = (a.y + b.y + d.y + e.y) * 0.25f;
        r.z = (a.z + b.z + d.z + e.z) * 0.25f;
        r.w = (a.w + b.w + d.w + e.w) * 0.25f;
        __stcs(out + i, r);

        a = na; b = nb; d = nd; e = ne;
    }
}

extern "C" void kernel_launch(void* const* d_in, const int* in_sizes, int n_in,
                              void* d_out, int out_size) {
    const float4* x = (const float4*)d_in[0];
    float4* out = (float4*)d_out;

    spectral_blurrin_kernel<<<NBLK, THREADS>>>(x, out);
}